// round 1
// baseline (speedup 1.0000x reference)
#include <cuda_runtime.h>

// y[tok][o] = sum_e cos(x[tok][e] + theta[e]) * W[o][e],  E = 16
// tok = 128*8192 = 1,048,576 tokens. Pure streaming: 64B in + 64B out per token.

#define BLK 256
#define TPT 2   // tokens per thread

__device__ __forceinline__ unsigned long long pack2(float a, float b) {
    unsigned long long r;
    asm("mov.b64 %0, {%1, %2};" : "=l"(r) : "f"(a), "f"(b));
    return r;
}
__device__ __forceinline__ void unpack2(unsigned long long v, float& a, float& b) {
    asm("mov.b64 {%0, %1}, %2;" : "=f"(a), "=f"(b) : "l"(v));
}
__device__ __forceinline__ unsigned long long ffma2(unsigned long long a,
                                                    unsigned long long b,
                                                    unsigned long long c) {
    unsigned long long d;
    asm("fma.rn.f32x2 %0, %1, %2, %3;" : "=l"(d) : "l"(a), "l"(b), "l"(c));
    return d;
}

__global__ __launch_bounds__(BLK)
void qmha_kernel(const float4* __restrict__ x4,
                 const float* __restrict__ theta,
                 const float* __restrict__ w,      // [16][16] row-major: w[o][e]
                 float4* __restrict__ out4,
                 int ntok)
{
    // Wt[e][o] so a column of W (all o for fixed e) is 16 contiguous floats.
    __shared__ float s_wT[16 * 16];
    __shared__ float s_th[16];

    const int tid = threadIdx.x;
    if (tid < 256) {
        const int o = tid >> 4;
        const int e = tid & 15;
        s_wT[e * 16 + o] = w[tid];
    }
    if (tid < 16) s_th[tid] = theta[tid];
    __syncthreads();

    // theta in registers (broadcast reads, conflict-free)
    float th[16];
#pragma unroll
    for (int j = 0; j < 16; j++) th[j] = s_th[j];

    const int gid      = blockIdx.x * BLK + tid;
    const int nthreads = gridDim.x * BLK;

    int  tok[TPT];
    bool ok[TPT];
    float z[TPT][16];

#pragma unroll
    for (int k = 0; k < TPT; k++) {
        tok[k] = gid + k * nthreads;
        ok[k]  = tok[k] < ntok;
        if (ok[k]) {
            const size_t base = (size_t)tok[k] * 4;
#pragma unroll
            for (int j = 0; j < 4; j++) {
                const float4 v = x4[base + j];
                z[k][4 * j + 0] = __cosf(v.x + th[4 * j + 0]);
                z[k][4 * j + 1] = __cosf(v.y + th[4 * j + 1]);
                z[k][4 * j + 2] = __cosf(v.z + th[4 * j + 2]);
                z[k][4 * j + 3] = __cosf(v.w + th[4 * j + 3]);
            }
        } else {
#pragma unroll
            for (int j = 0; j < 16; j++) z[k][j] = 0.0f;
        }
    }

    // acc[k][op] holds outputs (2*op, 2*op+1) for token k as packed f32x2
    unsigned long long acc[TPT][8];
    const unsigned long long zero2 = pack2(0.0f, 0.0f);
#pragma unroll
    for (int k = 0; k < TPT; k++)
#pragma unroll
        for (int op = 0; op < 8; op++) acc[k][op] = zero2;

#pragma unroll
    for (int e = 0; e < 16; e++) {
        // 8 x 64-bit broadcast loads of the W column for this e (uniform addr)
        const unsigned long long* wp =
            reinterpret_cast<const unsigned long long*>(s_wT + e * 16);
        unsigned long long wv[8];
#pragma unroll
        for (int op = 0; op < 8; op++) wv[op] = wp[op];

#pragma unroll
        for (int k = 0; k < TPT; k++) {
            const unsigned long long zz = pack2(z[k][e], z[k][e]);
#pragma unroll
            for (int op = 0; op < 8; op++)
                acc[k][op] = ffma2(zz, wv[op], acc[k][op]);
        }
    }

#pragma unroll
    for (int k = 0; k < TPT; k++) {
        if (ok[k]) {
            const size_t base = (size_t)tok[k] * 4;
#pragma unroll
            for (int j = 0; j < 4; j++) {
                float a0, a1, b0, b1;
                unpack2(acc[k][2 * j + 0], a0, a1);
                unpack2(acc[k][2 * j + 1], b0, b1);
                out4[base + j] = make_float4(a0, a1, b0, b1);
            }
        }
    }
}

extern "C" void kernel_launch(void* const* d_in, const int* in_sizes, int n_in,
                              void* d_out, int out_size) {
    const float* x     = (const float*)d_in[0];   // [B, S, 16] f32
    const float* theta = (const float*)d_in[1];   // [16] f32
    const float* w     = (const float*)d_in[2];   // [16, 16] f32
    float* out         = (float*)d_out;           // [B, S, 16] f32

    const int ntok   = in_sizes[0] / 16;
    const int blocks = (ntok + BLK * TPT - 1) / (BLK * TPT);

    qmha_kernel<<<blocks, BLK>>>((const float4*)x, theta, w, (float4*)out, ntok);
}

// round 3
// speedup vs baseline: 1.2476x; 1.2476x over previous
#include <cuda_runtime.h>

// y[tok][o] = sum_e cos(x[tok][e] + theta[e]) * W[o][e],  E = 16, ntok = 1,048,576
//
// Layout: warp processes 8 tokens ("octet") per step. lane = 4*q + i:
//   q = token-in-octet (0..7), i = component slice (0..3).
//   lane loads/stores the 16B slice [4i..4i+4) of token q -> fully coalesced 512B warp accesses.
//   W rows [4i..4i+4) live in registers (loaded once). z gathered across quad via shfl.

#define BLK 128
#define U   4   // octets per warp iteration (front-batched loads)

__device__ __forceinline__ unsigned long long pack2(float a, float b) {
    unsigned long long r;
    asm("mov.b64 %0, {%1, %2};" : "=l"(r) : "f"(a), "f"(b));
    return r;
}
__device__ __forceinline__ void unpack2(unsigned long long v, float& a, float& b) {
    asm("mov.b64 {%0, %1}, %2;" : "=f"(a), "=f"(b) : "l"(v));
}
__device__ __forceinline__ unsigned long long ffma2(unsigned long long a,
                                                    unsigned long long b,
                                                    unsigned long long c) {
    unsigned long long d;
    asm("fma.rn.f32x2 %0, %1, %2, %3;" : "=l"(d) : "l"(a), "l"(b), "l"(c));
    return d;
}

__global__ __launch_bounds__(BLK, 4)
void qmha_kernel(const float4* __restrict__ x4,
                 const float* __restrict__ theta,
                 const float* __restrict__ w,      // [16][16] row-major w[o][e]
                 float4* __restrict__ out4,
                 int ntok)
{
    __shared__ float sW[256];

    const int tid  = threadIdx.x;
    const int lane = tid & 31;
    const int i    = lane & 3;    // component slice
    const int q    = lane >> 2;   // token within octet

    // stage W through shared once
    sW[tid * 2 + 0] = w[tid * 2 + 0];
    sW[tid * 2 + 1] = w[tid * 2 + 1];
    __syncthreads();

    // W rows [4i..4i+4), packed per e as output-pairs: (r0,r1),(r2,r3)
    unsigned long long Wp[16][2];
    {
        const int r0 = 4 * i;
#pragma unroll
        for (int e = 0; e < 16; e++) {
            Wp[e][0] = pack2(sW[(r0 + 0) * 16 + e], sW[(r0 + 1) * 16 + e]);
            Wp[e][1] = pack2(sW[(r0 + 2) * 16 + e], sW[(r0 + 3) * 16 + e]);
        }
    }
    const float4 th = reinterpret_cast<const float4*>(theta)[i];

    const int warp_id = blockIdx.x * (BLK / 32) + (tid >> 5);
    const int nwarps  = gridDim.x * (BLK / 32);
    const int noct    = (ntok + 7) >> 3;
    const int ngrp    = (noct + U - 1) / U;

    for (int g = warp_id; g < ngrp; g += nwarps) {
        const int oct0 = g * U;
        // uniform full/partial-group test (ntok divisible by 8*U in practice:
        // the partial path never executes, but stays correct for odd sizes)
        const bool full = (oct0 * 8 + U * 8) <= ntok;

        float4 xv[U];
        if (full) {
#pragma unroll
            for (int u = 0; u < U; u++)
                xv[u] = x4[(size_t)(oct0 + u) * 32 + lane];
        } else {
#pragma unroll
            for (int u = 0; u < U; u++) {
                const int tok = (oct0 + u) * 8 + q;
                xv[u] = (tok < ntok) ? x4[(size_t)(oct0 + u) * 32 + lane]
                                     : make_float4(0.f, 0.f, 0.f, 0.f);
            }
        }

        float4 yv[U];
#pragma unroll
        for (int u = 0; u < U; u++) {
            // cos on own slice
            float4 zv;
            zv.x = __cosf(xv[u].x + th.x);
            zv.y = __cosf(xv[u].y + th.y);
            zv.z = __cosf(xv[u].z + th.z);
            zv.w = __cosf(xv[u].w + th.w);

            // all-gather z within the quad: z[4j+c] from quad member j
            float z[16];
#pragma unroll
            for (int j = 0; j < 4; j++) {
                z[4 * j + 0] = __shfl_sync(0xFFFFFFFFu, zv.x, j, 4);
                z[4 * j + 1] = __shfl_sync(0xFFFFFFFFu, zv.y, j, 4);
                z[4 * j + 2] = __shfl_sync(0xFFFFFFFFu, zv.z, j, 4);
                z[4 * j + 3] = __shfl_sync(0xFFFFFFFFu, zv.w, j, 4);
            }

            // 4 outputs per lane as 2 packed f32x2 accumulators
            unsigned long long a0 = pack2(0.f, 0.f);
            unsigned long long a1 = a0;
#pragma unroll
            for (int e = 0; e < 16; e++) {
                const unsigned long long zz = pack2(z[e], z[e]);
                a0 = ffma2(zz, Wp[e][0], a0);
                a1 = ffma2(zz, Wp[e][1], a1);
            }
            unpack2(a0, yv[u].x, yv[u].y);
            unpack2(a1, yv[u].z, yv[u].w);
        }

        if (full) {
#pragma unroll
            for (int u = 0; u < U; u++)
                out4[(size_t)(oct0 + u) * 32 + lane] = yv[u];
        } else {
#pragma unroll
            for (int u = 0; u < U; u++) {
                const int tok = (oct0 + u) * 8 + q;
                if (tok < ntok)
                    out4[(size_t)(oct0 + u) * 32 + lane] = yv[u];
            }
        }
    }
}

extern "C" void kernel_launch(void* const* d_in, const int* in_sizes, int n_in,
                              void* d_out, int out_size) {
    const float* x     = (const float*)d_in[0];   // [B, S, 16] f32
    const float* theta = (const float*)d_in[1];   // [16] f32
    const float* w     = (const float*)d_in[2];   // [16, 16] f32
    float* out         = (float*)d_out;           // [B, S, 16] f32

    const int ntok = in_sizes[0] / 16;

    const int noct = (ntok + 7) >> 3;
    const int ngrp = (noct + U - 1) / U;
    int blocks = (ngrp + (BLK / 32) - 1) / (BLK / 32);
    // balance across 148 SMs at 4 resident blocks each (launch_bounds),
    // 2 grid-stride passes max keeps tail skew tiny
    const int cap = 148 * 8;
    if (blocks > cap) blocks = cap;

    qmha_kernel<<<blocks, BLK>>>((const float4*)x, theta, w, (float4*)out, ntok);
}

// round 4
// speedup vs baseline: 1.3959x; 1.1189x over previous
#include <cuda_runtime.h>

// y[tok][o] = sum_e cos(x[tok][e] + theta[e]) * W[o][e],  E = 16, ntok = 1,048,576
//
// Warp handles 8 tokens per step. lane = 4*q + i: quad q works on token q,
// lane-slice i covers components/outputs [4i..4i+4). Fully coalesced 512B
// warp loads/stores. W lives in registers (permuted per-lane to match the
// butterfly gather order). z exchanged as packed f32x2 e-pairs via shfl.xor.

#define BLK 128
#define U   4

__device__ __forceinline__ unsigned long long pack2(float a, float b) {
    unsigned long long r;
    asm("mov.b64 %0, {%1, %2};" : "=l"(r) : "f"(a), "f"(b));
    return r;
}
__device__ __forceinline__ void unpack2(unsigned long long v, float& a, float& b) {
    asm("mov.b64 {%0, %1}, %2;" : "=f"(a), "=f"(b) : "l"(v));
}
__device__ __forceinline__ unsigned long long ffma2(unsigned long long a,
                                                    unsigned long long b,
                                                    unsigned long long c) {
    unsigned long long d;
    asm("fma.rn.f32x2 %0, %1, %2, %3;" : "=l"(d) : "l"(a), "l"(b), "l"(c));
    return d;
}
__device__ __forceinline__ unsigned long long shflx64(unsigned long long v, int m) {
    return __shfl_xor_sync(0xFFFFFFFFu, v, m, 4);
}

__global__ __launch_bounds__(BLK, 4)
void qmha_kernel(const float4* __restrict__ x4,
                 const float* __restrict__ theta,
                 const float* __restrict__ w,      // [16][16] row-major w[o][e]
                 float4* __restrict__ out4,
                 int ntok)
{
    __shared__ float sW[256];

    const int tid  = threadIdx.x;
    const int lane = tid & 31;
    const int i    = lane & 3;    // slice within quad
    const int q    = lane >> 2;   // token within octet

    sW[tid * 2 + 0] = w[tid * 2 + 0];
    sW[tid * 2 + 1] = w[tid * 2 + 1];
    __syncthreads();

    // W packed by e-pairs, in BUTTERFLY ARRIVAL ORDER:
    //   slot s holds e-block (i ^ s); within slot, h=0 -> e={4b,4b+1}, h=1 -> e={4b+2,4b+3}
    //   Wc[s][h][r] = { W[4i+r][4b+2h], W[4i+r][4b+2h+1] },  b = i^s
    unsigned long long Wc[4][2][4];
#pragma unroll
    for (int s = 0; s < 4; s++) {
        const int b = i ^ s;
#pragma unroll
        for (int h = 0; h < 2; h++) {
            const int e0 = 4 * b + 2 * h;
#pragma unroll
            for (int r = 0; r < 4; r++)
                Wc[s][h][r] = pack2(sW[(4 * i + r) * 16 + e0],
                                    sW[(4 * i + r) * 16 + e0 + 1]);
        }
    }
    const float4 th = reinterpret_cast<const float4*>(theta)[i];

    const int warp_id = blockIdx.x * (BLK / 32) + (tid >> 5);
    const int nwarps  = gridDim.x * (BLK / 32);
    const int noct    = (ntok + 7) >> 3;
    const int ngrp    = (noct + U - 1) / U;

    for (int g = warp_id; g < ngrp; g += nwarps) {
        const int oct0 = g * U;
        const bool full = (oct0 * 8 + U * 8) <= ntok;

        float4 xv[U];
        if (full) {
#pragma unroll
            for (int u = 0; u < U; u++)
                xv[u] = __ldcs(&x4[(size_t)(oct0 + u) * 32 + lane]);
        } else {
#pragma unroll
            for (int u = 0; u < U; u++) {
                const int tok = (oct0 + u) * 8 + q;
                xv[u] = (tok < ntok) ? __ldcs(&x4[(size_t)(oct0 + u) * 32 + lane])
                                     : make_float4(0.f, 0.f, 0.f, 0.f);
            }
        }

#pragma unroll
        for (int u = 0; u < U; u++) {
            // own slice: cos, pack into 2 e-pairs
            const unsigned long long p0 = pack2(__cosf(xv[u].x + th.x),
                                                __cosf(xv[u].y + th.y));
            const unsigned long long p1 = pack2(__cosf(xv[u].z + th.z),
                                                __cosf(xv[u].w + th.w));

            // butterfly all-gather within quad: 6 x 64-bit shfl = 12 SHFL.32
            const unsigned long long q0 = shflx64(p0, 1);
            const unsigned long long q1 = shflx64(p1, 1);
            const unsigned long long r0 = shflx64(p0, 2);
            const unsigned long long r1 = shflx64(p1, 2);
            const unsigned long long s0 = shflx64(q0, 2);
            const unsigned long long s1 = shflx64(q1, 2);

            // acc[r]: f32x2 partial sums over (even-e, odd-e) for output 4i+r
            unsigned long long acc[4];
#pragma unroll
            for (int r = 0; r < 4; r++) {
                acc[r] = ffma2(p0, Wc[0][0][r], pack2(0.f, 0.f));
                acc[r] = ffma2(p1, Wc[0][1][r], acc[r]);
                acc[r] = ffma2(q0, Wc[1][0][r], acc[r]);
                acc[r] = ffma2(q1, Wc[1][1][r], acc[r]);
                acc[r] = ffma2(r0, Wc[2][0][r], acc[r]);
                acc[r] = ffma2(r1, Wc[2][1][r], acc[r]);
                acc[r] = ffma2(s0, Wc[3][0][r], acc[r]);
                acc[r] = ffma2(s1, Wc[3][1][r], acc[r]);
            }

            float4 yv;
            {
                float a, b;
                unpack2(acc[0], a, b); yv.x = a + b;
                unpack2(acc[1], a, b); yv.y = a + b;
                unpack2(acc[2], a, b); yv.z = a + b;
                unpack2(acc[3], a, b); yv.w = a + b;
            }

            if (full || ((oct0 + u) * 8 + q) < ntok)
                __stcs(&out4[(size_t)(oct0 + u) * 32 + lane], yv);
        }
    }
}

extern "C" void kernel_launch(void* const* d_in, const int* in_sizes, int n_in,
                              void* d_out, int out_size) {
    const float* x     = (const float*)d_in[0];   // [B, S, 16] f32
    const float* theta = (const float*)d_in[1];   // [16] f32
    const float* w     = (const float*)d_in[2];   // [16, 16] f32
    float* out         = (float*)d_out;           // [B, S, 16] f32

    const int ntok = in_sizes[0] / 16;

    const int noct = (ntok + 7) >> 3;
    const int ngrp = (noct + U - 1) / U;
    int blocks = (ngrp + (BLK / 32) - 1) / (BLK / 32);
    const int cap = 148 * 8;
    if (blocks > cap) blocks = cap;

    qmha_kernel<<<blocks, BLK>>>((const float4*)x, theta, w, (float4*)out, ntok);
}